// round 12
// baseline (speedup 1.0000x reference)
#include <cuda_runtime.h>
#include <cstdint>

// DDK_77644418777653 — per-row recurrence scan, double-buffered pipeline via
// 4-byte cp.async (alignment-free w.r.t. the odd smem stride).
//
// out[:,0] = 1 ; out[:,k] = out[:,k-1] + alpha/out[:,k-1] - beta*in[:,k-1]
// M = 262144 rows, N = 512 cols, fp32, row-major.
//
// Block = 256 rows (thread = row). Columns in 32 tiles of 16. Tile t+1 is
// fetched with cp.async.ca (4B transfers -> no 16B smem-alignment constraint,
// unlike R7) into the alternate buffer while tile t computes/stores, so each
// CTA keeps a continuous DRAM read stream through the serial-divide phase.
//
// Bank maps (LDSR = 17, odd):
//   compute:  sm[tid*17 + i]            -> 17*tid mod 32 bijective, 32 banks
//   staging:  word idx = it*256 + tid, r = idx>>4, c = idx&15
//             warp = 2 rows x 16 cols -> banks 17r+{0..15} U 17r+{17..32}:
//             one 2-way pair per warp, rest conflict-free (vs R8's float4
//             map which was 2-way everywhere)
//   gmem:     16 consecutive lanes touch 64B contiguous -> fully coalesced
//
// fp semantics are bit-exact vs XLA:GPU's lowering (rel_err=0.0 since R6 —
// do NOT change):
//   t  = div.rn(a, w)
//   u  = add.rn(w, t)
//   w' = ffma.rn(-b, x, u)

#define ROWS   256
#define TK     16
#define LDSR   17
#define NCOLS  512
#define NT     (NCOLS / TK)          // 32 tiles
#define IT     (ROWS * TK / ROWS)    // 16 words per thread per tile

__device__ __forceinline__ void cpa4(uint32_t saddr, const float* g) {
    asm volatile("cp.async.ca.shared.global [%0], [%1], 4;"
                 :: "r"(saddr), "l"(g));
}

__global__ __launch_bounds__(ROWS)
void DDK_77644418777653_kernel(const float* __restrict__ in,
                               const float* __restrict__ alpha,
                               const float* __restrict__ beta,
                               float* __restrict__ out) {
    __shared__ float sm[2][ROWS * LDSR];   // 2 x 17408 B = 34816 B

    const int tid  = threadIdx.x;
    const int row0 = blockIdx.x * ROWS;

    const float a = alpha[0];
    const float b = beta[0];

    // Scalar staging geometry: word idx = it*256 + tid
    //   smem word  = (it*16 + (tid>>4)) * LDSR + (tid&15) = it*(16*LDSR) + soff
    //   gmem word  = (row0 + it*16 + (tid>>4)) * NCOLS + k0 + (tid&15)
    //              = gbase + k0 + it*(16*NCOLS)
    const int    soff  = (tid >> 4) * LDSR + (tid & 15);
    const size_t gbase = (size_t)(row0 + (tid >> 4)) * NCOLS + (tid & 15);

    const uint32_t sb[2] = {
        (uint32_t)__cvta_generic_to_shared(&sm[0][0]),
        (uint32_t)__cvta_generic_to_shared(&sm[1][0])
    };

    // ---- prologue: async-fetch tile 0 into buffer 0 ----
    #pragma unroll
    for (int it = 0; it < IT; ++it)
        cpa4(sb[0] + (uint32_t)(soff + it * (16 * LDSR)) * 4u,
             in + gbase + (size_t)it * (16 * NCOLS));
    asm volatile("cp.async.commit_group;");

    float w     = 1.0f;   // recurrence state for this thread's row
    float xprev = 0.0f;   // input value carried across tile boundary
    bool  first = true;   // col 0 of the whole row is exactly 1

    for (int t = 0; t < NT; ++t) {
        float* cur = sm[t & 1];

        // ---- issue async fetch of tile t+1 into the other buffer ----
        // (that buffer was last read by store(t-1), fenced by the trailing
        //  __syncthreads of the previous iteration)
        if (t + 1 < NT) {
            const uint32_t sdst = sb[(t + 1) & 1];
            const int      k1   = (t + 1) * TK;
            #pragma unroll
            for (int it = 0; it < IT; ++it)
                cpa4(sdst + (uint32_t)(soff + it * (16 * LDSR)) * 4u,
                     in + gbase + k1 + (size_t)it * (16 * NCOLS));
            asm volatile("cp.async.commit_group;");
            asm volatile("cp.async.wait_group 1;");  // tile t's group complete
        } else {
            asm volatile("cp.async.wait_group 0;");  // last group complete
        }
        __syncthreads();   // tile t visible to all threads

        // ---- per-thread serial recurrence over tile t (in-place) ----
        float* mrow = &cur[tid * LDSR];
        #pragma unroll
        for (int i = 0; i < TK; ++i) {
            float x = mrow[i];  // input col t*TK+i (read before overwrite)
            // out col uses input col-1 = xprev. Exact XLA op sequence.
            float u  = __fadd_rn(w, __fdiv_rn(a, w));
            float wn = __fmaf_rn(-b, xprev, u);
            w = first ? 1.0f : wn;
            mrow[i] = w;
            xprev   = x;
            first   = false;     // constant-folds away for i >= 1
        }
        __syncthreads();   // compute writes visible before cross-row store reads

        // ---- coalesced scalar store of tile t ----
        {
            const int k0 = t * TK;
            #pragma unroll
            for (int it = 0; it < IT; ++it)
                out[gbase + k0 + (size_t)it * (16 * NCOLS)] =
                    cur[soff + it * (16 * LDSR)];
        }
        __syncthreads();   // store reads done before group(t+2) overwrites cur
    }
}

extern "C" void kernel_launch(void* const* d_in, const int* in_sizes, int n_in,
                              void* d_out, int out_size) {
    const float* in    = (const float*)d_in[0];   // [262144, 512] fp32
    const float* alpha = (const float*)d_in[1];   // [1]
    const float* beta  = (const float*)d_in[2];   // [1]
    float*       out   = (float*)d_out;           // [262144, 512] fp32

    const int M = in_sizes[0] / NCOLS;            // 262144
    DDK_77644418777653_kernel<<<M / ROWS, ROWS>>>(in, alpha, beta, out);
}

// round 15
// speedup vs baseline: 1.4567x; 1.4567x over previous
#include <cuda_runtime.h>

// DDK_77644418777653 — per-row recurrence scan, transposed-tile SMEM staging.
//
// out[:,0] = 1 ; out[:,k] = out[:,k-1] + alpha/out[:,k-1] - beta*in[:,k-1]
// M = 262144 rows, N = 512 cols, fp32, row-major.
//
// Identical data path to the verified R6 kernel (200.8us, rel_err=0.0), with
// ROWS 256 -> 128: 16.9 KB smem / 4 warps per CTA -> ~13 CTAs/SM (vs 4).
// The load/compute/store phases of a CTA are barrier-serialized, so DRAM
// goes idle while a CTA computes; with 13 independent CTAs per SM the phases
// stagger statistically and the read/write streams stay continuous. Grid
// becomes 2048 CTAs = one ~full wave + 6% tail (vs R6's 73%-full 2nd wave).
//
// Bank maps (verified, TK=32):
//   staging: warp = 4 rows x 8 float4-slots, bank = (r + 4c) mod 32 -> all 32
//   compute: stride 33 (odd) -> 32 distinct banks
//
// fp semantics are bit-exact vs XLA:GPU's lowering (rel_err=0.0 since R6 —
// do NOT change):
//   t  = div.rn(a, w)
//   u  = add.rn(w, t)
//   w' = ffma.rn(-b, x, u)

#define ROWS   128
#define TK     32
#define LDSR   33              // padded smem row stride (odd -> conflict-free)
#define NCOLS  512
#define N4     (NCOLS / 4)
#define LD_IT  ((ROWS * TK / 4) / ROWS)   // 8 float4 slots per thread per tile

__global__ __launch_bounds__(ROWS)
void DDK_77644418777653_kernel(const float* __restrict__ in,
                               const float* __restrict__ alpha,
                               const float* __restrict__ beta,
                               float* __restrict__ out) {
    __shared__ float sm[ROWS * LDSR];   // 16896 B

    const int tid  = threadIdx.x;
    const int row0 = blockIdx.x * ROWS;

    const float a = alpha[0];
    const float b = beta[0];

    const float4* in4  = reinterpret_cast<const float4*>(in);
    float4*       out4 = reinterpret_cast<float4*>(out);

    // Staging slots this thread services: idx = it*ROWS + tid,
    // r = idx>>3 (4 consecutive rows per warp), c4 = idx&7.
    int rr[LD_IT], cc[LD_IT];
    #pragma unroll
    for (int it = 0; it < LD_IT; ++it) {
        int idx = it * ROWS + tid;
        rr[it] = idx >> 3;
        cc[it] = idx & 7;
    }

    float w     = 1.0f;   // recurrence state for this thread's row
    float xprev = 0.0f;   // input value carried across tile boundary
    bool  first = true;   // col 0 of the whole row is exactly 1

    for (int t = 0; t < NCOLS / TK; ++t) {
        const int kc4 = t * (TK / 4);

        // ---- coalesced load: 8 LDG.128 front-batched, then STS ----
        {
            float4 pf[LD_IT];
            #pragma unroll
            for (int it = 0; it < LD_IT; ++it)
                pf[it] = in4[(size_t)(row0 + rr[it]) * N4 + kc4 + cc[it]];
            #pragma unroll
            for (int it = 0; it < LD_IT; ++it) {
                float* d = &sm[rr[it] * LDSR + cc[it] * 4];
                d[0] = pf[it].x; d[1] = pf[it].y;
                d[2] = pf[it].z; d[3] = pf[it].w;
            }
        }
        __syncthreads();

        // ---- per-thread serial recurrence over this tile (in-place) ----
        float* mrow = &sm[tid * LDSR];
        #pragma unroll
        for (int i = 0; i < TK; ++i) {
            float x = mrow[i];  // input col t*TK+i (read before overwrite)
            // out col uses input col-1 = xprev. Exact XLA op sequence.
            float u  = __fadd_rn(w, __fdiv_rn(a, w));
            float wn = __fmaf_rn(-b, xprev, u);
            w = first ? 1.0f : wn;
            mrow[i] = w;
            xprev   = x;
            first   = false;     // constant-folds away for i >= 1
        }
        __syncthreads();

        // ---- coalesced store of the tile ----
        #pragma unroll
        for (int it = 0; it < LD_IT; ++it) {
            const float* s = &sm[rr[it] * LDSR + cc[it] * 4];
            out4[(size_t)(row0 + rr[it]) * N4 + kc4 + cc[it]] =
                make_float4(s[0], s[1], s[2], s[3]);
        }
        __syncthreads();   // smem reads done before next tile's STS overwrite
    }
}

extern "C" void kernel_launch(void* const* d_in, const int* in_sizes, int n_in,
                              void* d_out, int out_size) {
    const float* in    = (const float*)d_in[0];   // [262144, 512] fp32
    const float* alpha = (const float*)d_in[1];   // [1]
    const float* beta  = (const float*)d_in[2];   // [1]
    float*       out   = (float*)d_out;           // [262144, 512] fp32

    const int M = in_sizes[0] / NCOLS;            // 262144
    DDK_77644418777653_kernel<<<M / ROWS, ROWS>>>(in, alpha, beta, out);
}